// round 4
// baseline (speedup 1.0000x reference)
#include <cuda_runtime.h>
#include <cstdint>

#define NEG   (-1e30f)
#define LOG2E (1.4426950408889634f)
#define LN2   (0.6931471805599453f)

// Fixed problem shape (B=32, T=1024, V=1000, L=128); scratch sized to max.
#define MAXB 32
#define MAXT 1024
#define MAXL 128
#define ESTR 132   // padded emission row stride (floats): 129 used

// Static scratch (no allocation allowed anywhere).
__device__ float g_emit[(size_t)MAXB * MAXT * ESTR];
__device__ float g_res[MAXB];

__device__ __forceinline__ float lse2_2(float a, float b) {
    float m = fmaxf(a, b);
    float s = exp2f(a - m) + exp2f(b - m);
    return m + __log2f(s);
}
__device__ __forceinline__ float lse3_2(float a, float b, float c) {
    float m = fmaxf(a, fmaxf(b, c));
    float s = exp2f(a - m) + exp2f(b - m) + exp2f(c - m);
    return m + __log2f(s);
}

// ---------------------------------------------------------------------------
// Kernel A: one WARP per (b,t) row. Single pass over V=1000 in registers,
// warp-shuffle reductions only. Emits log2-domain log-softmax for the 129
// needed tokens (blank + L labels) into g_emit.
// ---------------------------------------------------------------------------
__global__ void __launch_bounds__(128) lse_gather_kernel(
    const float* __restrict__ pred,
    const int*   __restrict__ target,
    int T, int V, int L, int nrows)
{
    const int warp = blockIdx.x * (blockDim.x >> 5) + (threadIdx.x >> 5);
    if (warp >= nrows) return;
    const int lane = threadIdx.x & 31;
    const int b = warp / T;

    const float* __restrict__ row = pred + (size_t)warp * V;
    const float4* __restrict__ row4 = (const float4*)row;
    const int nvec = V >> 2;     // 250

    float4 v[8];
    #pragma unroll
    for (int i = 0; i < 8; ++i) {
        const int idx = lane + (i << 5);
        v[i] = (idx < nvec) ? row4[idx] : make_float4(NEG, NEG, NEG, NEG);
    }

    float m = NEG;
    #pragma unroll
    for (int i = 0; i < 8; ++i)
        m = fmaxf(m, fmaxf(fmaxf(v[i].x, v[i].y), fmaxf(v[i].z, v[i].w)));
    #pragma unroll
    for (int o = 16; o > 0; o >>= 1) m = fmaxf(m, __shfl_xor_sync(0xffffffffu, m, o));

    const float m2 = m * LOG2E;
    float sum = 0.f;
    #pragma unroll
    for (int i = 0; i < 8; ++i) {
        sum += exp2f(fmaf(v[i].x, LOG2E, -m2)) + exp2f(fmaf(v[i].y, LOG2E, -m2))
             + exp2f(fmaf(v[i].z, LOG2E, -m2)) + exp2f(fmaf(v[i].w, LOG2E, -m2));
    }
    #pragma unroll
    for (int o = 16; o > 0; o >>= 1) sum += __shfl_xor_sync(0xffffffffu, sum, o);

    const float lse2 = m2 + __log2f(sum);   // log2(sum_v exp(x_v))

    float* __restrict__ erow = g_emit + (size_t)warp * ESTR;
    const int* __restrict__ tgt = target + (size_t)b * L;
    for (int j = lane; j <= L; j += 32) {
        const int tok = (j == 0) ? 0 : tgt[j - 1];
        erow[j] = fmaf(row[tok], LOG2E, -lse2);
    }
}

// ---------------------------------------------------------------------------
// Kernel B: W-CTC forward DP. One block per batch; one (blank,label) PAIR per
// thread (129 active threads, 5 warps). State data flows through registers +
// __shfl_up (one neighbor value serves both states); only 4 warp-edge floats
// per step cross through shared memory (parity double-buffered). endstar is
// accumulated in registers on threads tl-1 / tl (no serial endstar thread).
// ---------------------------------------------------------------------------
__global__ void __launch_bounds__(160) wctc_dp_kernel(
    const int* __restrict__ target,
    const int* __restrict__ tlen,
    int T, int L)
{
    const int b    = blockIdx.x;
    const int tid  = threadIdx.x;
    const int lane = tid & 31;
    const int w    = tid >> 5;          // 5 warps

    __shared__ float edgeL[2][6];       // lane-31 label per warp, parity-buffered
    __shared__ int   tg[MAXL];
    __shared__ float sFin[4];           // [ll, lb, accL, accB]

    for (int i0 = tid; i0 < L; i0 += blockDim.x) tg[i0] = target[(size_t)b * L + i0];
    __syncthreads();

    const int  tl       = tlen[b];
    const int  i        = tid;                 // pair index: blank s=2i+1, label s=2i+2
    const bool hasBlank = (i <= tl);           // tl <= L=128, thread 128 exists
    const bool hasLabel = (i <= tl - 1);       // label valid
    const bool skipOK   = (i == 0) || (i <= L - 1 && tg[i] != tg[(i > 0) ? (i - 1) : 0]);
    const bool isLL     = (i == tl - 1);       // owns last label state
    const bool isLB     = (i == tl);           // owns last blank state

    const float* __restrict__ erow = g_emit + (size_t)b * T * ESTR;
    const int jL = (i + 1 <= L) ? (i + 1) : 0; // label emission column (clamped)

    // ---- t = 0 init ----
    float blank = NEG, label = NEG;
    if (i == 0) { blank = erow[0]; label = erow[1]; }
    if (!hasBlank) blank = NEG;
    if (!hasLabel) label = NEG;
    float accL = NEG, accB = NEG;              // endstar partial sums

    if (lane == 31) edgeL[0][w] = label;

    // Emission prefetch queue (depth 2)
    float eL0 = 0.f, eL1 = 0.f, eB0 = 0.f, eB1 = 0.f;
    eL0 = erow[(size_t)1 * ESTR + jL];
    eB0 = erow[(size_t)1 * ESTR];
    if (T > 2) { eL1 = erow[(size_t)2 * ESTR + jL]; eB1 = erow[(size_t)2 * ESTR]; }
    __syncthreads();

    for (int t = 1; t < T; ++t) {
        // prefetch t+2 first (overlaps ~2 iterations of compute)
        float eLn = 0.f, eBn = 0.f;
        if (t + 2 < T) {
            eLn = erow[(size_t)(t + 2) * ESTR + jL];
            eBn = erow[(size_t)(t + 2) * ESTR];
        }
        const int rp = (t - 1) & 1, wp = t & 1;

        // neighbor label (alpha_old[2i]); star (==0) for thread 0
        float nb = __shfl_up_sync(0xffffffffu, label, 1);
        if (lane == 0) nb = (w == 0) ? 0.0f : edgeL[rp][w - 1];

        // endstar absorbs alpha_{t-1}[ll], alpha_{t-1}[lb] (register lse2)
        if (isLL) accL = lse2_2(accL, label);
        if (isLB) accB = lse2_2(accB, blank);

        // blank update: e_blank + lse2(own blank, neighbor label)
        float nBlank = eB0 + lse2_2(blank, nb);
        if (!hasBlank) nBlank = NEG;

        // label update: e_label + lse3(own label, own blank, skip? neighbor : NEG)
        float p2 = skipOK ? nb : NEG;
        float nLabel = eL0 + lse3_2(label, blank, p2);
        if (!hasLabel) nLabel = NEG;

        if (lane == 31) edgeL[wp][w] = nLabel;

        blank = nBlank; label = nLabel;
        eL0 = eL1; eL1 = eLn; eB0 = eB1; eB1 = eBn;
        __syncthreads();
    }

    // ---- finalize ----
    if (isLL) { sFin[0] = label; sFin[2] = accL; }
    if (isLB) { sFin[1] = blank; sFin[3] = accB; }
    __syncthreads();
    if (tid == 0) {
        float endstar = lse2_2(sFin[2], sFin[3]);
        float tot2 = lse3_2(sFin[0], sFin[1], endstar);   // log2 total
        g_res[b] = (-tot2 * LN2) / (float)tl;             // nll / target_length
    }
}

// ---------------------------------------------------------------------------
// Kernel C: mean over batch -> scalar output.
// ---------------------------------------------------------------------------
__global__ void __launch_bounds__(32) finalize_kernel(float* __restrict__ out, int B)
{
    float v = 0.f;
    for (int i = threadIdx.x; i < B; i += 32) v += g_res[i];
    #pragma unroll
    for (int o = 16; o > 0; o >>= 1) v += __shfl_xor_sync(0xffffffffu, v, o);
    if (threadIdx.x == 0) out[0] = v / (float)B;
}

extern "C" void kernel_launch(void* const* d_in, const int* in_sizes, int n_in,
                              void* d_out, int out_size)
{
    const float* pred   = (const float*)d_in[0];   // (B,T,V) fp32
    const int*   target = (const int*)d_in[1];     // (B,L)  int32
    const int*   tlen   = (const int*)d_in[2];     // (B,)   int32

    const int B = in_sizes[2];
    const int L = in_sizes[1] / B;
    const int V = 1000;
    const int T = in_sizes[0] / (B * V);
    const int nrows = B * T;

    lse_gather_kernel<<<(nrows + 3) / 4, 128>>>(pred, target, T, V, L, nrows);
    wctc_dp_kernel<<<B, 160>>>(target, tlen, T, L);
    finalize_kernel<<<1, 32>>>((float*)d_out, B);
}

// round 6
// speedup vs baseline: 2.4445x; 2.4445x over previous
#include <cuda_runtime.h>
#include <cstdint>

#define NEG   (-1e30f)
#define LOG2E (1.4426950408889634f)
#define LN2   (0.6931471805599453f)

// Fixed problem shape (B=32, T=1024, V=1000, L=128); scratch sized to max.
#define MAXB 32
#define MAXT 1024
#define MAXL 128
#define ESTR 132     // padded emission row stride (floats): 129 used
#define CH   8       // timesteps staged per SMEM chunk
#define CHF  (CH * ESTR)        // floats per chunk (1056)
#define CHV  (CHF / 4)          // float4 per chunk (264)

// Static scratch (no allocation allowed anywhere).
__device__ float g_emit[(size_t)MAXB * MAXT * ESTR];
__device__ float g_res[MAXB];

__device__ __forceinline__ float lse3_2(float a, float b, float c) {
    // logsumexp in log2 domain: m + log2(2^(a-m)+2^(b-m)+2^(c-m))
    float m = fmaxf(a, fmaxf(b, c));
    float s = exp2f(a - m) + exp2f(b - m) + exp2f(c - m);
    return m + __log2f(s);
}

// ---------------------------------------------------------------------------
// Kernel A: one WARP per (b,t) row. Single pass over V=1000 in registers,
// warp-shuffle reductions only. Emits log2-domain log-softmax for the 129
// needed tokens (blank + L labels) into g_emit.
// ---------------------------------------------------------------------------
__global__ void __launch_bounds__(128) lse_gather_kernel(
    const float* __restrict__ pred,
    const int*   __restrict__ target,
    int T, int V, int L, int nrows)
{
    const int warp = blockIdx.x * (blockDim.x >> 5) + (threadIdx.x >> 5);
    if (warp >= nrows) return;
    const int lane = threadIdx.x & 31;
    const int b = warp / T;

    const float* __restrict__ row = pred + (size_t)warp * V;
    const float4* __restrict__ row4 = (const float4*)row;
    const int nvec = V >> 2;     // 250

    float4 v[8];
    #pragma unroll
    for (int i = 0; i < 8; ++i) {
        const int idx = lane + (i << 5);
        v[i] = (idx < nvec) ? row4[idx] : make_float4(NEG, NEG, NEG, NEG);
    }

    float m = NEG;
    #pragma unroll
    for (int i = 0; i < 8; ++i)
        m = fmaxf(m, fmaxf(fmaxf(v[i].x, v[i].y), fmaxf(v[i].z, v[i].w)));
    #pragma unroll
    for (int o = 16; o > 0; o >>= 1) m = fmaxf(m, __shfl_xor_sync(0xffffffffu, m, o));

    const float m2 = m * LOG2E;
    float sum = 0.f;
    #pragma unroll
    for (int i = 0; i < 8; ++i) {
        sum += exp2f(fmaf(v[i].x, LOG2E, -m2)) + exp2f(fmaf(v[i].y, LOG2E, -m2))
             + exp2f(fmaf(v[i].z, LOG2E, -m2)) + exp2f(fmaf(v[i].w, LOG2E, -m2));
    }
    #pragma unroll
    for (int o = 16; o > 0; o >>= 1) sum += __shfl_xor_sync(0xffffffffu, sum, o);

    const float lse2 = m2 + __log2f(sum);   // log2(sum_v exp(x_v))

    float* __restrict__ erow = g_emit + (size_t)warp * ESTR;
    const int* __restrict__ tgt = target + (size_t)b * L;
    for (int j = lane; j <= L; j += 32) {
        const int tok = (j == 0) ? 0 : tgt[j - 1];
        erow[j] = fmaf(row[tok], LOG2E, -lse2);
    }
}

// ---------------------------------------------------------------------------
// Kernel B: W-CTC forward DP, one block per batch, one thread per state
// (288 threads; 258 active states, tail threads idle/helper).
// Emissions staged through a double-buffered SMEM chunk of CH=8 timesteps:
// LDG for chunk c+1 issues at the start of chunk c (>=1100 cyc slack), so the
// per-step emission read is a conflict-free LDS. Log2-domain DP; shared
// double-buffered alpha; ONE __syncthreads per step. endstar is accumulated
// by an otherwise-idle tail thread (off the critical path).
// ---------------------------------------------------------------------------
#define ESTID 280

__global__ void __launch_bounds__(288) wctc_dp_kernel(
    const int* __restrict__ target,
    const int* __restrict__ tlen,
    int T, int L)
{
    const int b = blockIdx.x;
    const int tid = threadIdx.x;
    const int S = 2 * L + 2;                 // 258

    __shared__ float buf[2][2 * MAXL + 4];   // alpha double buffer; idx s+2, [0..1]=NEG
    __shared__ float e_sh[2][CHF];           // staged emission chunks
    __shared__ int   tg[MAXL];

    for (int i = tid; i < L; i += blockDim.x) tg[i] = target[(size_t)b * L + i];
    if (tid < 2) { buf[0][tid] = NEG; buf[1][tid] = NEG; }

    const int  tl      = tlen[b];
    const int  s       = tid;
    const bool active  = (s < S);
    const bool isStar  = (s == 0);
    const bool isBlank = ((s & 1) == 1);
    const bool isLab   = active && !isStar && !isBlank;
    const int  lab     = isLab ? ((s - 2) >> 1) : 0;
    const int  j       = isBlank ? 0 : (s >> 1);       // emission column (star ignores)
    const bool skipOK  = isLab && ((s == 2) || (tg[lab] != tg[lab - 1]));
    const bool validS  = (s <= 2 * tl + 1);
    const int  ll = 2 * tl, lb = ll + 1;

    const float*  __restrict__ erow  = g_emit + (size_t)b * T * ESTR;
    const float4* __restrict__ erow4 = (const float4*)erow;

    // t = 0 init
    if (active) {
        float a0 = NEG;
        if (s == 0)      a0 = 0.f;
        else if (s == 1) a0 = erow[0];
        else if (s == 2) a0 = erow[1];
        if (!validS)     a0 = NEG;
        buf[0][s + 2] = a0;
    }
    float endstar = NEG;                 // meaningful on thread ESTID only

    // Preload chunk 0 into registers
    float4 ld = make_float4(0.f, 0.f, 0.f, 0.f);
    if (tid < CHV) ld = erow4[tid];

    const int nchunks = T / CH;          // 128
    int cur = 0;

    for (int c = 0; c < nchunks; ++c) {
        // Stage previously-loaded chunk, then issue LDG for the next one.
        const int pb = c & 1;
        if (tid < CHV) ((float4*)e_sh[pb])[tid] = ld;
        if (c + 1 < nchunks && tid < CHV)
            ld = erow4[(size_t)(c + 1) * CHV + tid];
        __syncthreads();

        const float* __restrict__ E = e_sh[pb];

        #pragma unroll
        for (int tc = 0; tc < CH; ++tc) {
            const int t = c * CH + tc;
            if (t == 0) continue;        // uniform across block

            float* C  = buf[cur];
            float* Nx = buf[cur ^ 1];
            if (active) {
                float a  = C[s + 2];
                float p1 = C[s + 1];
                float p2 = skipOK ? C[s] : NEG;
                float r  = lse3_2(a, p1, p2);
                float ev = isStar ? 0.f : E[tc * ESTR + j];
                Nx[s + 2] = validS ? (ev + r) : NEG;
            }
            if (tid == ESTID)            // off-critical-path endstar absorb
                endstar = lse3_2(endstar, C[ll + 2], C[lb + 2]);
            __syncthreads();
            cur ^= 1;
        }
    }

    if (tid == ESTID) {
        float* C = buf[cur];
        float tot2 = lse3_2(C[ll + 2], C[lb + 2], endstar);  // log2 total
        g_res[b] = (-tot2 * LN2) / (float)tl;                // nll / target_length
    }
}

// ---------------------------------------------------------------------------
// Kernel C: mean over batch -> scalar output.
// ---------------------------------------------------------------------------
__global__ void __launch_bounds__(32) finalize_kernel(float* __restrict__ out, int B)
{
    float v = 0.f;
    for (int i = threadIdx.x; i < B; i += 32) v += g_res[i];
    #pragma unroll
    for (int o = 16; o > 0; o >>= 1) v += __shfl_xor_sync(0xffffffffu, v, o);
    if (threadIdx.x == 0) out[0] = v / (float)B;
}

extern "C" void kernel_launch(void* const* d_in, const int* in_sizes, int n_in,
                              void* d_out, int out_size)
{
    const float* pred   = (const float*)d_in[0];   // (B,T,V) fp32
    const int*   target = (const int*)d_in[1];     // (B,L)  int32
    const int*   tlen   = (const int*)d_in[2];     // (B,)   int32

    const int B = in_sizes[2];
    const int L = in_sizes[1] / B;
    const int V = 1000;
    const int T = in_sizes[0] / (B * V);
    const int nrows = B * T;

    lse_gather_kernel<<<(nrows + 3) / 4, 128>>>(pred, target, T, V, L, nrows);
    wctc_dp_kernel<<<B, 288>>>(target, tlen, T, L);
    finalize_kernel<<<1, 32>>>((float*)d_out, B);
}